// round 16
// baseline (speedup 1.0000x reference)
#include <cuda_runtime.h>
#include <cuda_fp16.h>
#include <math.h>

// Problem constants (fixed by setup_inputs)
#define B_  4
#define T_  512
#define S_  512
#define D_  1024
#define V_  32000
#define E_  512
#define OUTW (V_ + E_)   // 32512
#define NROW (B_ * T_)   // 2048
#define KK2  (D_ / 2)    // 512 packed k-pairs
#define VH   (V_ / 2)    // 16000 column half
#define RH   (NROW / 2)  // 1024 row half

// ---------------- device scratch (no allocation allowed) ----------------
__device__ float g_pcopy[NROW];
__device__ float g_attn[NROW * S_];
__device__ int   g_srcidx[B_ * S_];
__device__ int   g_maskmode;
// fp16 hi/lo split, packed as u32 = (h16[k+1]<<16)|h16[k]
__device__ unsigned g_Ah[NROW * KK2];              // query hi,  [row][kk2]
__device__ unsigned g_Al[NROW * KK2];              // query lo
__device__ unsigned g_Wgh[(size_t)KK2 * V_];       // W_gen hi,  [kk2][n]
__device__ unsigned g_Winh[KK2 * 1024];            // W_in hi,   [kk2][n]
__device__ unsigned g_Winl[KK2 * 1024];            // W_in lo
__device__ unsigned g_Qih[NROW * KK2];             // qin hi,    [row][kk2]
__device__ unsigned g_Qil[NROW * KK2];             // qin lo
__device__ unsigned g_Mbh[B_ * KK2 * S_];          // membank^T hi, [b][kk2][s]
__device__ unsigned g_Mbl[B_ * KK2 * S_];          // membank^T lo

// ---------------- small helpers ----------------
__device__ __forceinline__ unsigned smaddr(const void* p) {
    return (unsigned)__cvta_generic_to_shared(p);
}
__device__ __forceinline__ void cp16(unsigned dst, const void* src) {
    asm volatile("cp.async.cg.shared.global [%0], [%1], 16;\n" :: "r"(dst), "l"(src));
}
__device__ __forceinline__ void cp_commit() {
    asm volatile("cp.async.commit_group;\n" ::);
}
template<int N> __device__ __forceinline__ void cp_wait() {
    asm volatile("cp.async.wait_group %0;\n" :: "n"(N));
}
// fp16 hi/lo split: x = hi + lo with |lo| <= 2^-12 |x|
__device__ __forceinline__ void pack_hilo(float x0, float x1, unsigned &hi, unsigned &lo) {
    __half h0 = __float2half_rn(x0);
    __half h1 = __float2half_rn(x1);
    __half l0 = __float2half_rn(x0 - __half2float(h0));
    __half l1 = __float2half_rn(x1 - __half2float(h1));
    __half2 ph; ph.x = h0; ph.y = h1;
    __half2 pl; pl.x = l0; pl.y = l1;
    hi = *reinterpret_cast<unsigned*>(&ph);
    lo = *reinterpret_cast<unsigned*>(&pl);
}
__device__ __forceinline__ unsigned pack_hi_only(float x0, float x1) {
    __half2 ph; ph.x = __float2half_rn(x0); ph.y = __float2half_rn(x1);
    return *reinterpret_cast<unsigned*>(&ph);
}

#define MMA16816(d, a0, a1, a2, a3, b0, b1)                                     \
    asm volatile("mma.sync.aligned.m16n8k16.row.col.f32.f16.f16.f32 "           \
        "{%0,%1,%2,%3},{%4,%5,%6,%7},{%8,%9},{%0,%1,%2,%3};"                    \
        : "+f"(d[0]), "+f"(d[1]), "+f"(d[2]), "+f"(d[3])                        \
        : "r"(a0), "r"(a1), "r"(a2), "r"(a3), "r"(b0), "r"(b1))

__device__ __forceinline__ void ldmA(unsigned &r0, unsigned &r1, unsigned &r2,
                                     unsigned &r3, unsigned addr) {
    asm volatile("ldmatrix.sync.aligned.m8n8.x4.shared.b16 {%0,%1,%2,%3}, [%4];"
        : "=r"(r0), "=r"(r1), "=r"(r2), "=r"(r3) : "r"(addr));
}

// ---------------- block reductions ----------------
__device__ __forceinline__ float blockReduceMax(float v) {
    __shared__ float s[33];
    int lane = threadIdx.x & 31, wid = threadIdx.x >> 5;
    #pragma unroll
    for (int o = 16; o; o >>= 1) v = fmaxf(v, __shfl_down_sync(0xffffffffu, v, o));
    if (lane == 0) s[wid] = v;
    __syncthreads();
    int nw = (blockDim.x + 31) >> 5;
    v = (threadIdx.x < (unsigned)nw) ? s[threadIdx.x] : -INFINITY;
    if (wid == 0) {
        #pragma unroll
        for (int o = 16; o; o >>= 1) v = fmaxf(v, __shfl_down_sync(0xffffffffu, v, o));
        if (lane == 0) s[32] = v;
    }
    __syncthreads();
    float r = s[32];
    __syncthreads();
    return r;
}
__device__ __forceinline__ float blockReduceSum(float v) {
    __shared__ float s[33];
    int lane = threadIdx.x & 31, wid = threadIdx.x >> 5;
    #pragma unroll
    for (int o = 16; o; o >>= 1) v += __shfl_down_sync(0xffffffffu, v, o);
    if (lane == 0) s[wid] = v;
    __syncthreads();
    int nw = (blockDim.x + 31) >> 5;
    v = (threadIdx.x < (unsigned)nw) ? s[threadIdx.x] : 0.0f;
    if (wid == 0) {
        #pragma unroll
        for (int o = 16; o; o >>= 1) v += __shfl_down_sync(0xffffffffu, v, o);
        if (lane == 0) s[32] = v;
    }
    __syncthreads();
    float r = s[32];
    __syncthreads();
    return r;
}

// ---------------- mask dtype detection (parallel) ----------------
__global__ void detect_maskmode_kernel(const unsigned int* __restrict__ m) {
    __shared__ int s_f, s_i, s_nz;
    if (threadIdx.x == 0) { s_f = 1; s_i = 1; s_nz = 0; }
    __syncthreads();
    unsigned w = m[threadIdx.x];
    if (w) {
        atomicExch(&s_nz, 1);
        if (w != 0x3F800000u) atomicExch(&s_f, 0);
        if (w != 1u) atomicExch(&s_i, 0);
    }
    __syncthreads();
    if (threadIdx.x == 0)
        g_maskmode = (s_nz && s_f) ? 2 : ((s_nz && s_i) ? 1 : 0);
}

// ---------------- pack rows: fp32 [R][D] -> fp16 hi/lo [R][KK2] ----------------
__global__ __launch_bounds__(256)
void aconv_kernel(const float* __restrict__ src, unsigned* __restrict__ dh,
                  unsigned* __restrict__ dl) {
    size_t id = (size_t)blockIdx.x * 256 + threadIdx.x;
    float2 q2 = reinterpret_cast<const float2*>(src)[id];
    unsigned hi, lo;
    pack_hilo(q2.x, q2.y, hi, lo);
    dh[id] = hi; dl[id] = lo;
}

// ---------------- pack weights hi/lo: fp32 [D][N] -> fp16 [KK2][N] ----------------
__global__ __launch_bounds__(256)
void wconv_kernel(const float* __restrict__ W, unsigned* __restrict__ Ph,
                  unsigned* __restrict__ Pl, int N) {
    size_t id = (size_t)blockIdx.x * 256 + threadIdx.x;  // < KK2*N/2
    int half = N >> 1;
    size_t kk2 = id / (unsigned)half;
    size_t np = id - kk2 * (unsigned)half;
    size_t n = np * 2;
    float2 x0 = *reinterpret_cast<const float2*>(&W[(2 * kk2) * (size_t)N + n]);
    float2 x1 = *reinterpret_cast<const float2*>(&W[(2 * kk2 + 1) * (size_t)N + n]);
    uint2 h, l;
    pack_hilo(x0.x, x1.x, h.x, l.x);
    pack_hilo(x0.y, x1.y, h.y, l.y);
    *reinterpret_cast<uint2*>(&Ph[kk2 * (size_t)N + n]) = h;
    *reinterpret_cast<uint2*>(&Pl[kk2 * (size_t)N + n]) = l;
}

// ---------------- pack weights hi-only, column-chunked ----------------
__global__ __launch_bounds__(256)
void wconv_h_kernel(const float* __restrict__ W, unsigned* __restrict__ Ph,
                    int N, int nbase, int ncount) {
    size_t id = (size_t)blockIdx.x * 256 + threadIdx.x;  // < KK2*ncount/2
    int half = ncount >> 1;
    size_t kk2 = id / (unsigned)half;
    size_t np = id - kk2 * (unsigned)half;
    size_t n = nbase + np * 2;
    float2 x0 = *reinterpret_cast<const float2*>(&W[(2 * kk2) * (size_t)N + n]);
    float2 x1 = *reinterpret_cast<const float2*>(&W[(2 * kk2 + 1) * (size_t)N + n]);
    uint2 h;
    h.x = pack_hi_only(x0.x, x1.x);
    h.y = pack_hi_only(x0.y, x1.y);
    *reinterpret_cast<uint2*>(&Ph[kk2 * (size_t)N + n]) = h;
}

// ---------------- transpose-pack membank ----------------
__global__ __launch_bounds__(256)
void packMbT_kernel(const float* __restrict__ mb) {
    unsigned id = blockIdx.x * 256 + threadIdx.x;
    unsigned b = id / (KK2 * S_);
    unsigned rem = id - b * (KK2 * S_);
    unsigned kk2 = rem / S_;
    unsigned n = rem - kk2 * S_;
    float2 v = reinterpret_cast<const float2*>(mb)[((size_t)b * S_ + n) * KK2 + kk2];
    unsigned hi, lo;
    pack_hilo(v.x, v.y, hi, lo);
    g_Mbh[id] = hi; g_Mbl[id] = lo;
}

// ---------------- fp16 multi-pass tensor-core GEMM, templated M tile ----------------
// NPASS=3: C = Ah*Bh + Ah*Bl + Al*Bh ; NPASS=1: C = Ah*Bh (Al/Bl slots elided).
// OUTPACK=1: epilogue packs hi/lo u32 to Ph/Pl instead of fp32 C.
// MR = 128 (256 thr, 2 CTA/SM) or 256 (512 thr, 1 CTA/SM) — 512 threads/SM either way.
#define A_STR 20
#define B_STR 136
#define SB (16 * B_STR)

template<int NPASS, int OUTPACK, int MR>
__global__ __launch_bounds__(MR * 2, 256 / MR)
void gemm_f16x(const unsigned* __restrict__ Ah_, const unsigned* __restrict__ Al_,
               const unsigned* __restrict__ Bh_, const unsigned* __restrict__ Bl_,
               int N, const float* __restrict__ bias,
               float* __restrict__ C_, int ldc,
               unsigned* __restrict__ Ph, unsigned* __restrict__ Pl,
               long long aOffZ, long long bOffZ, long long cOffZ) {
    constexpr int NT = MR * 2;                       // threads
    constexpr int SA_ = MR * A_STR;                  // A hi smem u32
    constexpr int SAT = (NPASS >= 3 ? 2 : 1) * SA_;  // A region total
    constexpr int STG = SAT + (NPASS >= 2 ? 2 : 1) * SB;
    extern __shared__ unsigned sm[];
    const unsigned* Ah = Ah_ + (size_t)blockIdx.z * aOffZ;
    const unsigned* Al = Al_ + (size_t)blockIdx.z * aOffZ;
    const unsigned* Bh = Bh_ + (size_t)blockIdx.z * bOffZ;
    const unsigned* Bl = Bl_ + (size_t)blockIdx.z * bOffZ;
    float* C = C_ + (size_t)blockIdx.z * cOffZ;
    const int tid = threadIdx.x;
    const int m0 = blockIdx.x * MR, n0 = blockIdx.y * 128;
    const int warp = tid >> 5, lane = tid & 31;
    const int wm = (warp >> 2) * 64;
    const int wn = (warp & 3) * 32;
    const int lr = lane >> 2;
    const int lc = lane & 3;

    float acc[4][4][4];
    #pragma unroll
    for (int i = 0; i < 4; i++)
        #pragma unroll
        for (int j = 0; j < 4; j++)
            #pragma unroll
            for (int c = 0; c < 4; c++) acc[i][j][c] = 0.0f;

    auto stage_load = [&](int k0, int buf) {
        unsigned* s = sm + buf * STG;
        // A: MR rows x 4 chunks = MR*4 = 2*NT chunks
        #pragma unroll
        for (int r = 0; r < 2; r++) {
            int c = tid + NT * r;
            int row = c >> 2, q = (c & 3) * 4;
            size_t gsrc = (size_t)(m0 + row) * KK2 + k0 * 16 + q;
            cp16(smaddr(s + row * A_STR + q), Ah + gsrc);
            if (NPASS >= 3)
                cp16(smaddr(s + SA_ + row * A_STR + q), Al + gsrc);
        }
        // B: 512 chunks
        #pragma unroll
        for (int r = 0; r < 512 / NT; r++) {
            int c = tid + NT * r;
            int kk = c >> 5, q = (c & 31) * 4;
            size_t gsrc = (size_t)(k0 * 16 + kk) * (size_t)N + n0 + q;
            cp16(smaddr(s + SAT + kk * B_STR + q), Bh + gsrc);
            if (NPASS >= 2)
                cp16(smaddr(s + SAT + SB + kk * B_STR + q), Bl + gsrc);
        }
        cp_commit();
    };

    const unsigned a_lane_off = (((wm + (lane & 15)) * A_STR + (lane >> 4) * 4) << 2);

    const int KT = D_ / 32;
    stage_load(0, 0);
    for (int k0 = 0; k0 < KT; k0++) {
        if (k0 + 1 < KT) { stage_load(k0 + 1, (k0 + 1) & 1); cp_wait<1>(); }
        else cp_wait<0>();
        __syncthreads();
        unsigned* s = sm + (k0 & 1) * STG;
        unsigned* sBh = s + SAT;
        unsigned* sBl = s + SAT + SB;
        const unsigned aBase = smaddr(s) + a_lane_off;
        #pragma unroll
        for (int ss = 0; ss < 2; ss++) {
            const int ka = ss * 8 + lc;
            unsigned bh[4][2], bl[4][2];
            #pragma unroll
            for (int j = 0; j < 4; j++) {
                int cc = wn + j * 8 + lr;
                bh[j][0] = sBh[ka * B_STR + cc];
                bh[j][1] = sBh[(ka + 4) * B_STR + cc];
                if (NPASS >= 2) {
                    bl[j][0] = sBl[ka * B_STR + cc];
                    bl[j][1] = sBl[(ka + 4) * B_STR + cc];
                }
            }
            #pragma unroll
            for (int i = 0; i < 4; i++) {
                unsigned ad = aBase + i * (16 * A_STR * 4) + ss * 32;
                unsigned a0, a1, a2, a3;
                ldmA(a0, a1, a2, a3, ad);
                unsigned c0 = 0, c1 = 0, c2 = 0, c3 = 0;
                if (NPASS >= 3)
                    ldmA(c0, c1, c2, c3, ad + SA_ * 4);
                #pragma unroll
                for (int j = 0; j < 4; j++) {
                    MMA16816(acc[i][j], a0, a1, a2, a3, bh[j][0], bh[j][1]);
                    if (NPASS >= 2)
                        MMA16816(acc[i][j], a0, a1, a2, a3, bl[j][0], bl[j][1]);
                    if (NPASS >= 3)
                        MMA16816(acc[i][j], c0, c1, c2, c3, bh[j][0], bh[j][1]);
                }
            }
        }
        __syncthreads();
    }

    // epilogue
    #pragma unroll
    for (int i = 0; i < 4; i++) {
        int row = m0 + wm + i * 16 + lr;
        #pragma unroll
        for (int j = 0; j < 4; j++) {
            int col = n0 + wn + j * 8 + lc * 2;
            if (OUTPACK) {
                unsigned h0, l0, h1, l1;
                pack_hilo(acc[i][j][0], acc[i][j][1], h0, l0);
                pack_hilo(acc[i][j][2], acc[i][j][3], h1, l1);
                size_t o0 = (size_t)row * KK2 + (col >> 1);
                size_t o1 = (size_t)(row + 8) * KK2 + (col >> 1);
                Ph[o0] = h0; Pl[o0] = l0;
                Ph[o1] = h1; Pl[o1] = l1;
            } else {
                float b0 = 0.f, b1 = 0.f;
                if (bias) { b0 = bias[col]; b1 = bias[col + 1]; }
                C[(size_t)row * ldc + col]           = acc[i][j][0] + b0;
                C[(size_t)row * ldc + col + 1]       = acc[i][j][1] + b1;
                C[(size_t)(row + 8) * ldc + col]     = acc[i][j][2] + b0;
                C[(size_t)(row + 8) * ldc + col + 1] = acc[i][j][3] + b1;
            }
        }
    }
}

#define SMEM_OF(NP, MRV) \
    (2 * (((NP) >= 3 ? 2 : 1) * ((MRV) * A_STR) + ((NP) >= 2 ? 2 : 1) * SB) * 4)

// ---------------- p_copy gate ----------------
__global__ __launch_bounds__(256)
void pcopy_kernel(const float* __restrict__ query,
                  const float* __restrict__ Wc,
                  const float* __restrict__ bc) {
    int row = blockIdx.x;
    float p = 0.f;
    #pragma unroll
    for (int i = 0; i < D_ / 256; i++) {
        int d = threadIdx.x + i * 256;
        p += query[(size_t)row * D_ + d] * Wc[d];
    }
    float sum = blockReduceSum(p);
    if (threadIdx.x == 0) {
        float x = sum + bc[0];
        g_pcopy[row] = 1.0f / (1.0f + expf(-x));
    }
}

// ---------------- one-hot -> index ----------------
__global__ __launch_bounds__(512)
void srcidx_kernel(const float* __restrict__ src_map) {
    int bs = blockIdx.x;
    float v = src_map[(size_t)bs * E_ + threadIdx.x];
    if (v > 0.5f) g_srcidx[bs] = threadIdx.x;
}

// ---------------- masked softmax over S + scatter ----------------
__global__ __launch_bounds__(512)
void attn_softmax_scatter(const void* __restrict__ src_pad_mask,
                          float* __restrict__ out) {
    __shared__ float acc[E_];
    int row = blockIdx.x;
    int b = row / T_;
    int s = threadIdx.x;
    int mi = b * S_ + s;
    int mode = g_maskmode;
    bool masked;
    if (mode == 2)      masked = ((const float*)src_pad_mask)[mi] != 0.0f;
    else if (mode == 1) masked = ((const int*)src_pad_mask)[mi] != 0;
    else                masked = ((const unsigned char*)src_pad_mask)[mi] != 0;
    float v = g_attn[(size_t)row * S_ + s];
    if (masked) v = -1e18f;
    float mx = blockReduceMax(v);
    float e = expf(v - mx);
    float sum = blockReduceSum(e);
    float p = e / sum * g_pcopy[row];
    acc[threadIdx.x] = 0.0f;
    __syncthreads();
    atomicAdd(&acc[g_srcidx[mi]], p);
    __syncthreads();
    out[(size_t)row * OUTW + V_ + threadIdx.x] = acc[threadIdx.x];
}

// ---------------- big softmax over V (float4, fast exp), row-chunked ----------------
#define NIT4 8
__global__ __launch_bounds__(1024)
void gen_softmax(float* __restrict__ out, int rbase) {
    const int NV4 = V_ / 4;
    int row = rbase + blockIdx.x;
    float* p = out + (size_t)row * OUTW;
    float4 vals[NIT4];
    float mx = -INFINITY;
    #pragma unroll
    for (int i = 0; i < NIT4; i++) {
        int idx = i * 1024 + threadIdx.x;
        if (idx < NV4) {
            float4 v = reinterpret_cast<const float4*>(p)[idx];
            if (idx == 0) v.x = -1e-20f;
            vals[i] = v;
            mx = fmaxf(fmaxf(fmaxf(mx, v.x), fmaxf(v.y, v.z)), v.w);
        } else {
            vals[i] = make_float4(-INFINITY, -INFINITY, -INFINITY, -INFINITY);
        }
    }
    mx = blockReduceMax(mx);
    float sum = 0.f;
    #pragma unroll
    for (int i = 0; i < NIT4; i++) {
        int idx = i * 1024 + threadIdx.x;
        if (idx < NV4) {
            float4 v = vals[i];
            v.x = __expf(v.x - mx); v.y = __expf(v.y - mx);
            v.z = __expf(v.z - mx); v.w = __expf(v.w - mx);
            vals[i] = v;
            sum += v.x + v.y + v.z + v.w;
        }
    }
    sum = blockReduceSum(sum);
    float scale = (1.0f - g_pcopy[row]) / sum;
    #pragma unroll
    for (int i = 0; i < NIT4; i++) {
        int idx = i * 1024 + threadIdx.x;
        if (idx < NV4) {
            float4 v = vals[i];
            v.x *= scale; v.y *= scale; v.z *= scale; v.w *= scale;
            reinterpret_cast<float4*>(p)[idx] = v;
        }
    }
}

// ---------------- stream/event setup ----------------
struct StreamInit {
    cudaStream_t s1, s2;
    cudaEvent_t evFork, evA, evJoin, evW1, evR0, evS0;
    StreamInit() {
        cudaStreamCreateWithFlags(&s1, cudaStreamNonBlocking);
        cudaStreamCreateWithFlags(&s2, cudaStreamNonBlocking);
        cudaEventCreateWithFlags(&evFork, cudaEventDisableTiming);
        cudaEventCreateWithFlags(&evA, cudaEventDisableTiming);
        cudaEventCreateWithFlags(&evJoin, cudaEventDisableTiming);
        cudaEventCreateWithFlags(&evW1, cudaEventDisableTiming);
        cudaEventCreateWithFlags(&evR0, cudaEventDisableTiming);
        cudaEventCreateWithFlags(&evS0, cudaEventDisableTiming);
    }
};
static StreamInit g_si;

// ---------------- launch ----------------
extern "C" void kernel_launch(void* const* d_in, const int* in_sizes, int n_in,
                              void* d_out, int out_size) {
    const float* query   = (const float*)d_in[0];
    const float* membank = (const float*)d_in[1];
    const void*  mask    = d_in[2];
    const float* src_map = (const float*)d_in[3];
    const float* W_in    = (const float*)d_in[4];
    const float* W_copy  = (const float*)d_in[5];
    const float* b_copy  = (const float*)d_in[6];
    const float* W_gen   = (const float*)d_in[7];
    const float* b_gen   = (const float*)d_in[8];
    float* out = (float*)d_out;

    void *p_Ah = 0, *p_Al = 0, *p_Wgh = 0;
    void *p_Winh = 0, *p_Winl = 0, *p_Qih = 0, *p_Qil = 0, *p_Mbh = 0, *p_Mbl = 0;
    void *p_attn = 0;
    cudaGetSymbolAddress(&p_attn, g_attn);
    cudaGetSymbolAddress(&p_Ah, g_Ah);
    cudaGetSymbolAddress(&p_Al, g_Al);
    cudaGetSymbolAddress(&p_Wgh, g_Wgh);
    cudaGetSymbolAddress(&p_Winh, g_Winh);
    cudaGetSymbolAddress(&p_Winl, g_Winl);
    cudaGetSymbolAddress(&p_Qih, g_Qih);
    cudaGetSymbolAddress(&p_Qil, g_Qil);
    cudaGetSymbolAddress(&p_Mbh, g_Mbh);
    cudaGetSymbolAddress(&p_Mbl, g_Mbl);

    static bool attr_set = false;
    if (!attr_set) {
        cudaFuncSetAttribute((void*)gemm_f16x<3, 0, 128>, cudaFuncAttributeMaxDynamicSharedMemorySize, SMEM_OF(3, 128));
        cudaFuncSetAttribute((void*)gemm_f16x<3, 1, 128>, cudaFuncAttributeMaxDynamicSharedMemorySize, SMEM_OF(3, 128));
        cudaFuncSetAttribute((void*)gemm_f16x<1, 0, 256>, cudaFuncAttributeMaxDynamicSharedMemorySize, SMEM_OF(1, 256));
        attr_set = true;
    }

    cudaStream_t s0 = 0;
    cudaStream_t s1 = g_si.s1;
    cudaStream_t s2 = g_si.s2;

    // ---- fork ----
    cudaEventRecord(g_si.evFork, s0);

    // ---- stream 0: shared prerequisites ----
    aconv_kernel<<<(NROW * KK2) / 256, 256, 0, s0>>>(query, (unsigned*)p_Ah, (unsigned*)p_Al);
    pcopy_kernel<<<NROW, 256, 0, s0>>>(query, W_copy, b_copy);
    cudaEventRecord(g_si.evA, s0);

    // ---- stream 2: pack second half of W_gen ----
    cudaStreamWaitEvent(s2, g_si.evFork, 0);
    wconv_h_kernel<<<(KK2 * VH / 2) / 256, 256, 0, s2>>>(W_gen, (unsigned*)p_Wgh, V_, VH, VH);
    cudaEventRecord(g_si.evW1, s2);

    // ---- stream 1: attention branch ----
    cudaStreamWaitEvent(s1, g_si.evFork, 0);
    detect_maskmode_kernel<<<1, 512, 0, s1>>>((const unsigned int*)mask);
    srcidx_kernel<<<B_ * S_, 512, 0, s1>>>(src_map);
    wconv_kernel<<<(KK2 * 1024 / 2) / 256, 256, 0, s1>>>(W_in, (unsigned*)p_Winh, (unsigned*)p_Winl, 1024);
    packMbT_kernel<<<(B_ * KK2 * S_) / 256, 256, 0, s1>>>(membank);
    cudaStreamWaitEvent(s1, g_si.evA, 0);
    // qin = query @ W_in (fp16x3), epilogue packs hi/lo into Qih/Qil
    gemm_f16x<3, 1, 128><<<dim3(NROW / 128, 1024 / 128, 1), 256, SMEM_OF(3, 128), s1>>>(
        (const unsigned*)p_Ah, (const unsigned*)p_Al,
        (const unsigned*)p_Winh, (const unsigned*)p_Winl,
        1024, nullptr, nullptr, 0,
        (unsigned*)p_Qih, (unsigned*)p_Qil, 0, 0, 0);
    // attention logits per batch (fp16x3, z-batched)
    gemm_f16x<3, 0, 128><<<dim3(T_ / 128, S_ / 128, B_), 256, SMEM_OF(3, 128), s1>>>(
        (const unsigned*)p_Qih, (const unsigned*)p_Qil,
        (const unsigned*)p_Mbh, (const unsigned*)p_Mbl,
        S_, nullptr, (float*)p_attn, S_, nullptr, nullptr,
        (long long)T_ * KK2, (long long)KK2 * S_, (long long)T_ * S_);
    attn_softmax_scatter<<<NROW, 512, 0, s1>>>(mask, out);
    cudaEventRecord(g_si.evJoin, s1);

    // ---- stream 0: pipelined gen chain (2 row-halves x 2 col-halves), M=256 tiles ----
    wconv_h_kernel<<<(KK2 * VH / 2) / 256, 256, 0, s0>>>(W_gen, (unsigned*)p_Wgh, V_, 0, VH);
    // G(r0, c0)
    gemm_f16x<1, 0, 256><<<dim3(RH / 256, VH / 128, 1), 512, SMEM_OF(1, 256), s0>>>(
        (const unsigned*)p_Ah, (const unsigned*)p_Al,
        (const unsigned*)p_Wgh, (const unsigned*)p_Wgh,
        V_, b_gen, out, OUTW, nullptr, nullptr, 0, 0, 0);
    // G(r0, c1)
    cudaStreamWaitEvent(s0, g_si.evW1, 0);
    gemm_f16x<1, 0, 256><<<dim3(RH / 256, VH / 128, 1), 512, SMEM_OF(1, 256), s0>>>(
        (const unsigned*)p_Ah, (const unsigned*)p_Al,
        (const unsigned*)p_Wgh + VH, (const unsigned*)p_Wgh + VH,
        V_, b_gen + VH, out + VH, OUTW, nullptr, nullptr, 0, 0, 0);
    cudaEventRecord(g_si.evR0, s0);
    // G(r1, c0), G(r1, c1)
    gemm_f16x<1, 0, 256><<<dim3(RH / 256, VH / 128, 1), 512, SMEM_OF(1, 256), s0>>>(
        (const unsigned*)p_Ah + (size_t)RH * KK2, (const unsigned*)p_Al,
        (const unsigned*)p_Wgh, (const unsigned*)p_Wgh,
        V_, b_gen, out + (size_t)RH * OUTW, OUTW, nullptr, nullptr, 0, 0, 0);
    gemm_f16x<1, 0, 256><<<dim3(RH / 256, VH / 128, 1), 512, SMEM_OF(1, 256), s0>>>(
        (const unsigned*)p_Ah + (size_t)RH * KK2, (const unsigned*)p_Al,
        (const unsigned*)p_Wgh + VH, (const unsigned*)p_Wgh + VH,
        V_, b_gen + VH, out + (size_t)RH * OUTW + VH, OUTW, nullptr, nullptr, 0, 0, 0);
    // softmax(r0) on s2, overlapping r1 GEMMs
    cudaStreamWaitEvent(s2, g_si.evR0, 0);
    gen_softmax<<<RH, 1024, 0, s2>>>(out, 0);
    cudaEventRecord(g_si.evS0, s2);
    // softmax(r1) on s0
    gen_softmax<<<RH, 1024, 0, s0>>>(out, RH);

    // ---- join ----
    cudaStreamWaitEvent(s0, g_si.evS0, 0);
    cudaStreamWaitEvent(s0, g_si.evJoin, 0);
}

// round 17
// speedup vs baseline: 1.1904x; 1.1904x over previous
#include <cuda_runtime.h>
#include <cuda_fp16.h>
#include <math.h>

// Problem constants (fixed by setup_inputs)
#define B_  4
#define T_  512
#define S_  512
#define D_  1024
#define V_  32000
#define E_  512
#define OUTW (V_ + E_)   // 32512
#define NROW (B_ * T_)   // 2048
#define KK2  (D_ / 2)    // 512 packed k-pairs
#define VH   (V_ / 2)    // 16000 column half
#define RH   (NROW / 2)  // 1024 row half

// ---------------- device scratch (no allocation allowed) ----------------
__device__ float g_pcopy[NROW];
__device__ float g_attn[NROW * S_];
__device__ int   g_srcidx[B_ * S_];
__device__ int   g_maskmode;
// fp16 hi/lo split, packed as u32 = (h16[k+1]<<16)|h16[k]
__device__ unsigned g_Ah[NROW * KK2];              // query hi,  [row][kk2]
__device__ unsigned g_Al[NROW * KK2];              // query lo
__device__ unsigned g_Wgh[(size_t)KK2 * V_];       // W_gen hi,  [kk2][n]
__device__ unsigned g_Winh[KK2 * 1024];            // W_in hi,   [kk2][n]
__device__ unsigned g_Winl[KK2 * 1024];            // W_in lo
__device__ unsigned g_Qih[NROW * KK2];             // qin hi,    [row][kk2]
__device__ unsigned g_Qil[NROW * KK2];             // qin lo
__device__ unsigned g_Mbh[B_ * KK2 * S_];          // membank^T hi, [b][kk2][s]
__device__ unsigned g_Mbl[B_ * KK2 * S_];          // membank^T lo

// ---------------- small helpers ----------------
__device__ __forceinline__ unsigned smaddr(const void* p) {
    return (unsigned)__cvta_generic_to_shared(p);
}
__device__ __forceinline__ void cp16(unsigned dst, const void* src) {
    asm volatile("cp.async.cg.shared.global [%0], [%1], 16;\n" :: "r"(dst), "l"(src));
}
__device__ __forceinline__ void cp_commit() {
    asm volatile("cp.async.commit_group;\n" ::);
}
template<int N> __device__ __forceinline__ void cp_wait() {
    asm volatile("cp.async.wait_group %0;\n" :: "n"(N));
}
// fp16 hi/lo split: x = hi + lo with |lo| <= 2^-12 |x|
__device__ __forceinline__ void pack_hilo(float x0, float x1, unsigned &hi, unsigned &lo) {
    __half h0 = __float2half_rn(x0);
    __half h1 = __float2half_rn(x1);
    __half l0 = __float2half_rn(x0 - __half2float(h0));
    __half l1 = __float2half_rn(x1 - __half2float(h1));
    __half2 ph; ph.x = h0; ph.y = h1;
    __half2 pl; pl.x = l0; pl.y = l1;
    hi = *reinterpret_cast<unsigned*>(&ph);
    lo = *reinterpret_cast<unsigned*>(&pl);
}
__device__ __forceinline__ unsigned pack_hi_only(float x0, float x1) {
    __half2 ph; ph.x = __float2half_rn(x0); ph.y = __float2half_rn(x1);
    return *reinterpret_cast<unsigned*>(&ph);
}

#define MMA16816(d, a0, a1, a2, a3, b0, b1)                                     \
    asm volatile("mma.sync.aligned.m16n8k16.row.col.f32.f16.f16.f32 "           \
        "{%0,%1,%2,%3},{%4,%5,%6,%7},{%8,%9},{%0,%1,%2,%3};"                    \
        : "+f"(d[0]), "+f"(d[1]), "+f"(d[2]), "+f"(d[3])                        \
        : "r"(a0), "r"(a1), "r"(a2), "r"(a3), "r"(b0), "r"(b1))

__device__ __forceinline__ void ldmA(unsigned &r0, unsigned &r1, unsigned &r2,
                                     unsigned &r3, unsigned addr) {
    asm volatile("ldmatrix.sync.aligned.m8n8.x4.shared.b16 {%0,%1,%2,%3}, [%4];"
        : "=r"(r0), "=r"(r1), "=r"(r2), "=r"(r3) : "r"(addr));
}

// ---------------- block reductions ----------------
__device__ __forceinline__ float blockReduceMax(float v) {
    __shared__ float s[33];
    int lane = threadIdx.x & 31, wid = threadIdx.x >> 5;
    #pragma unroll
    for (int o = 16; o; o >>= 1) v = fmaxf(v, __shfl_down_sync(0xffffffffu, v, o));
    if (lane == 0) s[wid] = v;
    __syncthreads();
    int nw = (blockDim.x + 31) >> 5;
    v = (threadIdx.x < (unsigned)nw) ? s[threadIdx.x] : -INFINITY;
    if (wid == 0) {
        #pragma unroll
        for (int o = 16; o; o >>= 1) v = fmaxf(v, __shfl_down_sync(0xffffffffu, v, o));
        if (lane == 0) s[32] = v;
    }
    __syncthreads();
    float r = s[32];
    __syncthreads();
    return r;
}
__device__ __forceinline__ float blockReduceSum(float v) {
    __shared__ float s[33];
    int lane = threadIdx.x & 31, wid = threadIdx.x >> 5;
    #pragma unroll
    for (int o = 16; o; o >>= 1) v += __shfl_down_sync(0xffffffffu, v, o);
    if (lane == 0) s[wid] = v;
    __syncthreads();
    int nw = (blockDim.x + 31) >> 5;
    v = (threadIdx.x < (unsigned)nw) ? s[threadIdx.x] : 0.0f;
    if (wid == 0) {
        #pragma unroll
        for (int o = 16; o; o >>= 1) v += __shfl_down_sync(0xffffffffu, v, o);
        if (lane == 0) s[32] = v;
    }
    __syncthreads();
    float r = s[32];
    __syncthreads();
    return r;
}

// ---------------- mask dtype detection (parallel) ----------------
__global__ void detect_maskmode_kernel(const unsigned int* __restrict__ m) {
    __shared__ int s_f, s_i, s_nz;
    if (threadIdx.x == 0) { s_f = 1; s_i = 1; s_nz = 0; }
    __syncthreads();
    unsigned w = m[threadIdx.x];
    if (w) {
        atomicExch(&s_nz, 1);
        if (w != 0x3F800000u) atomicExch(&s_f, 0);
        if (w != 1u) atomicExch(&s_i, 0);
    }
    __syncthreads();
    if (threadIdx.x == 0)
        g_maskmode = (s_nz && s_f) ? 2 : ((s_nz && s_i) ? 1 : 0);
}

// ---------------- pack rows: fp32 [R][D] -> fp16 hi/lo [R][KK2] ----------------
__global__ __launch_bounds__(256)
void aconv_kernel(const float* __restrict__ src, unsigned* __restrict__ dh,
                  unsigned* __restrict__ dl) {
    size_t id = (size_t)blockIdx.x * 256 + threadIdx.x;
    float2 q2 = reinterpret_cast<const float2*>(src)[id];
    unsigned hi, lo;
    pack_hilo(q2.x, q2.y, hi, lo);
    dh[id] = hi; dl[id] = lo;
}

// ---------------- pack weights hi/lo: fp32 [D][N] -> fp16 [KK2][N] ----------------
__global__ __launch_bounds__(256)
void wconv_kernel(const float* __restrict__ W, unsigned* __restrict__ Ph,
                  unsigned* __restrict__ Pl, int N) {
    size_t id = (size_t)blockIdx.x * 256 + threadIdx.x;  // < KK2*N/2
    int half = N >> 1;
    size_t kk2 = id / (unsigned)half;
    size_t np = id - kk2 * (unsigned)half;
    size_t n = np * 2;
    float2 x0 = *reinterpret_cast<const float2*>(&W[(2 * kk2) * (size_t)N + n]);
    float2 x1 = *reinterpret_cast<const float2*>(&W[(2 * kk2 + 1) * (size_t)N + n]);
    uint2 h, l;
    pack_hilo(x0.x, x1.x, h.x, l.x);
    pack_hilo(x0.y, x1.y, h.y, l.y);
    *reinterpret_cast<uint2*>(&Ph[kk2 * (size_t)N + n]) = h;
    *reinterpret_cast<uint2*>(&Pl[kk2 * (size_t)N + n]) = l;
}

// ---------------- pack weights hi-only, column-chunked ----------------
__global__ __launch_bounds__(256)
void wconv_h_kernel(const float* __restrict__ W, unsigned* __restrict__ Ph,
                    int N, int nbase, int ncount) {
    size_t id = (size_t)blockIdx.x * 256 + threadIdx.x;  // < KK2*ncount/2
    int half = ncount >> 1;
    size_t kk2 = id / (unsigned)half;
    size_t np = id - kk2 * (unsigned)half;
    size_t n = nbase + np * 2;
    float2 x0 = *reinterpret_cast<const float2*>(&W[(2 * kk2) * (size_t)N + n]);
    float2 x1 = *reinterpret_cast<const float2*>(&W[(2 * kk2 + 1) * (size_t)N + n]);
    uint2 h;
    h.x = pack_hi_only(x0.x, x1.x);
    h.y = pack_hi_only(x0.y, x1.y);
    *reinterpret_cast<uint2*>(&Ph[kk2 * (size_t)N + n]) = h;
}

// ---------------- transpose-pack membank ----------------
__global__ __launch_bounds__(256)
void packMbT_kernel(const float* __restrict__ mb) {
    unsigned id = blockIdx.x * 256 + threadIdx.x;
    unsigned b = id / (KK2 * S_);
    unsigned rem = id - b * (KK2 * S_);
    unsigned kk2 = rem / S_;
    unsigned n = rem - kk2 * S_;
    float2 v = reinterpret_cast<const float2*>(mb)[((size_t)b * S_ + n) * KK2 + kk2];
    unsigned hi, lo;
    pack_hilo(v.x, v.y, hi, lo);
    g_Mbh[id] = hi; g_Mbl[id] = lo;
}

// ---------------- fp16 multi-pass tensor-core GEMM (MR=128, 256 thr, 2 CTA/SM) ----------------
// NPASS=3: C = Ah*Bh + Ah*Bl + Al*Bh (2-stage, verified path, byte-identical to round 15)
// NPASS=1: C = Ah*Bh, NSTAGE=3 ring with single barrier per k-tile.
// OUTPACK=1: epilogue packs hi/lo u32 to Ph/Pl instead of fp32 C.
#define A_STR 20
#define B_STR 136
#define SA (128 * A_STR)
#define SB (16 * B_STR)

template<int NPASS, int OUTPACK, int NSTAGE>
__global__ __launch_bounds__(256, 2)
void gemm_f16x(const unsigned* __restrict__ Ah_, const unsigned* __restrict__ Al_,
               const unsigned* __restrict__ Bh_, const unsigned* __restrict__ Bl_,
               int N, const float* __restrict__ bias,
               float* __restrict__ C_, int ldc,
               unsigned* __restrict__ Ph, unsigned* __restrict__ Pl,
               long long aOffZ, long long bOffZ, long long cOffZ) {
    constexpr int SAT = (NPASS >= 3 ? 2 : 1) * SA;   // A region u32
    constexpr int STG = SAT + (NPASS >= 2 ? 2 : 1) * SB;
    extern __shared__ unsigned sm[];
    const unsigned* Ah = Ah_ + (size_t)blockIdx.z * aOffZ;
    const unsigned* Al = Al_ + (size_t)blockIdx.z * aOffZ;
    const unsigned* Bh = Bh_ + (size_t)blockIdx.z * bOffZ;
    const unsigned* Bl = Bl_ + (size_t)blockIdx.z * bOffZ;
    float* C = C_ + (size_t)blockIdx.z * cOffZ;
    const int tid = threadIdx.x;
    const int m0 = blockIdx.x * 128, n0 = blockIdx.y * 128;
    const int warp = tid >> 5, lane = tid & 31;
    const int wm = (warp >> 2) * 64;
    const int wn = (warp & 3) * 32;
    const int lr = lane >> 2;
    const int lc = lane & 3;

    float acc[4][4][4];
    #pragma unroll
    for (int i = 0; i < 4; i++)
        #pragma unroll
        for (int j = 0; j < 4; j++)
            #pragma unroll
            for (int c = 0; c < 4; c++) acc[i][j][c] = 0.0f;

    auto stage_load = [&](int k0, int buf) {
        unsigned* s = sm + buf * STG;
        #pragma unroll
        for (int r = 0; r < 2; r++) {
            int c = tid + 256 * r;
            int row = c >> 2, q = (c & 3) * 4;
            size_t gsrc = (size_t)(m0 + row) * KK2 + k0 * 16 + q;
            cp16(smaddr(s + row * A_STR + q), Ah + gsrc);
            if (NPASS >= 3)
                cp16(smaddr(s + SA + row * A_STR + q), Al + gsrc);
        }
        #pragma unroll
        for (int r = 0; r < 2; r++) {
            int c = tid + 256 * r;
            int kk = c >> 5, q = (c & 31) * 4;
            size_t gsrc = (size_t)(k0 * 16 + kk) * (size_t)N + n0 + q;
            cp16(smaddr(s + SAT + kk * B_STR + q), Bh + gsrc);
            if (NPASS >= 2)
                cp16(smaddr(s + SAT + SB + kk * B_STR + q), Bl + gsrc);
        }
        cp_commit();
    };

    const unsigned a_lane_off = (((wm + (lane & 15)) * A_STR + (lane >> 4) * 4) << 2);

    auto compute_tile = [&](int buf) {
        unsigned* s = sm + buf * STG;
        unsigned* sBh = s + SAT;
        unsigned* sBl = s + SAT + SB;
        const unsigned aBase = smaddr(s) + a_lane_off;
        #pragma unroll
        for (int ss = 0; ss < 2; ss++) {
            const int ka = ss * 8 + lc;
            unsigned bh[4][2], bl[4][2];
            #pragma unroll
            for (int j = 0; j < 4; j++) {
                int cc = wn + j * 8 + lr;
                bh[j][0] = sBh[ka * B_STR + cc];
                bh[j][1] = sBh[(ka + 4) * B_STR + cc];
                if (NPASS >= 2) {
                    bl[j][0] = sBl[ka * B_STR + cc];
                    bl[j][1] = sBl[(ka + 4) * B_STR + cc];
                }
            }
            #pragma unroll
            for (int i = 0; i < 4; i++) {
                unsigned ad = aBase + i * (16 * A_STR * 4) + ss * 32;
                unsigned a0, a1, a2, a3;
                ldmA(a0, a1, a2, a3, ad);
                unsigned c0 = 0, c1 = 0, c2 = 0, c3 = 0;
                if (NPASS >= 3)
                    ldmA(c0, c1, c2, c3, ad + SA * 4);
                #pragma unroll
                for (int j = 0; j < 4; j++) {
                    MMA16816(acc[i][j], a0, a1, a2, a3, bh[j][0], bh[j][1]);
                    if (NPASS >= 2)
                        MMA16816(acc[i][j], a0, a1, a2, a3, bl[j][0], bl[j][1]);
                    if (NPASS >= 3)
                        MMA16816(acc[i][j], c0, c1, c2, c3, bh[j][0], bh[j][1]);
                }
            }
        }
    };

    const int KT = D_ / 32;
    if constexpr (NSTAGE == 2) {
        // verified 2-stage schedule (round 15)
        stage_load(0, 0);
        for (int k0 = 0; k0 < KT; k0++) {
            if (k0 + 1 < KT) { stage_load(k0 + 1, (k0 + 1) & 1); cp_wait<1>(); }
            else cp_wait<0>();
            __syncthreads();
            compute_tile(k0 & 1);
            __syncthreads();
        }
    } else {
        // 3-stage ring, single barrier per tile
        stage_load(0, 0);
        stage_load(1, 1);
        #pragma unroll 4
        for (int k0 = 0; k0 < KT; k0++) {
            if (k0 < KT - 1) cp_wait<1>(); else cp_wait<0>();
            __syncthreads();
            // load into buffer (k0+2)%3 == (k0-1)%3, last read finished at k0-1
            if (k0 + 2 < KT) stage_load(k0 + 2, (k0 + 2) % 3);
            compute_tile(k0 % 3);
        }
    }

    // epilogue
    #pragma unroll
    for (int i = 0; i < 4; i++) {
        int row = m0 + wm + i * 16 + lr;
        #pragma unroll
        for (int j = 0; j < 4; j++) {
            int col = n0 + wn + j * 8 + lc * 2;
            if (OUTPACK) {
                unsigned h0, l0, h1, l1;
                pack_hilo(acc[i][j][0], acc[i][j][1], h0, l0);
                pack_hilo(acc[i][j][2], acc[i][j][3], h1, l1);
                size_t o0 = (size_t)row * KK2 + (col >> 1);
                size_t o1 = (size_t)(row + 8) * KK2 + (col >> 1);
                Ph[o0] = h0; Pl[o0] = l0;
                Ph[o1] = h1; Pl[o1] = l1;
            } else {
                float b0 = 0.f, b1 = 0.f;
                if (bias) { b0 = bias[col]; b1 = bias[col + 1]; }
                C[(size_t)row * ldc + col]           = acc[i][j][0] + b0;
                C[(size_t)row * ldc + col + 1]       = acc[i][j][1] + b1;
                C[(size_t)(row + 8) * ldc + col]     = acc[i][j][2] + b0;
                C[(size_t)(row + 8) * ldc + col + 1] = acc[i][j][3] + b1;
            }
        }
    }
}

#define SMEM_OF(NP, NS) \
    ((NS) * (((NP) >= 3 ? 2 : 1) * SA + ((NP) >= 2 ? 2 : 1) * SB) * 4)

// ---------------- p_copy gate ----------------
__global__ __launch_bounds__(256)
void pcopy_kernel(const float* __restrict__ query,
                  const float* __restrict__ Wc,
                  const float* __restrict__ bc) {
    int row = blockIdx.x;
    float p = 0.f;
    #pragma unroll
    for (int i = 0; i < D_ / 256; i++) {
        int d = threadIdx.x + i * 256;
        p += query[(size_t)row * D_ + d] * Wc[d];
    }
    float sum = blockReduceSum(p);
    if (threadIdx.x == 0) {
        float x = sum + bc[0];
        g_pcopy[row] = 1.0f / (1.0f + expf(-x));
    }
}

// ---------------- one-hot -> index ----------------
__global__ __launch_bounds__(512)
void srcidx_kernel(const float* __restrict__ src_map) {
    int bs = blockIdx.x;
    float v = src_map[(size_t)bs * E_ + threadIdx.x];
    if (v > 0.5f) g_srcidx[bs] = threadIdx.x;
}

// ---------------- masked softmax over S + scatter ----------------
__global__ __launch_bounds__(512)
void attn_softmax_scatter(const void* __restrict__ src_pad_mask,
                          float* __restrict__ out) {
    __shared__ float acc[E_];
    int row = blockIdx.x;
    int b = row / T_;
    int s = threadIdx.x;
    int mi = b * S_ + s;
    int mode = g_maskmode;
    bool masked;
    if (mode == 2)      masked = ((const float*)src_pad_mask)[mi] != 0.0f;
    else if (mode == 1) masked = ((const int*)src_pad_mask)[mi] != 0;
    else                masked = ((const unsigned char*)src_pad_mask)[mi] != 0;
    float v = g_attn[(size_t)row * S_ + s];
    if (masked) v = -1e18f;
    float mx = blockReduceMax(v);
    float e = expf(v - mx);
    float sum = blockReduceSum(e);
    float p = e / sum * g_pcopy[row];
    acc[threadIdx.x] = 0.0f;
    __syncthreads();
    atomicAdd(&acc[g_srcidx[mi]], p);
    __syncthreads();
    out[(size_t)row * OUTW + V_ + threadIdx.x] = acc[threadIdx.x];
}

// ---------------- big softmax over V (float4, fast exp), row-chunked ----------------
#define NIT4 8
__global__ __launch_bounds__(1024)
void gen_softmax(float* __restrict__ out, int rbase) {
    const int NV4 = V_ / 4;
    int row = rbase + blockIdx.x;
    float* p = out + (size_t)row * OUTW;
    float4 vals[NIT4];
    float mx = -INFINITY;
    #pragma unroll
    for (int i = 0; i < NIT4; i++) {
        int idx = i * 1024 + threadIdx.x;
        if (idx < NV4) {
            float4 v = reinterpret_cast<const float4*>(p)[idx];
            if (idx == 0) v.x = -1e-20f;
            vals[i] = v;
            mx = fmaxf(fmaxf(fmaxf(mx, v.x), fmaxf(v.y, v.z)), v.w);
        } else {
            vals[i] = make_float4(-INFINITY, -INFINITY, -INFINITY, -INFINITY);
        }
    }
    mx = blockReduceMax(mx);
    float sum = 0.f;
    #pragma unroll
    for (int i = 0; i < NIT4; i++) {
        int idx = i * 1024 + threadIdx.x;
        if (idx < NV4) {
            float4 v = vals[i];
            v.x = __expf(v.x - mx); v.y = __expf(v.y - mx);
            v.z = __expf(v.z - mx); v.w = __expf(v.w - mx);
            vals[i] = v;
            sum += v.x + v.y + v.z + v.w;
        }
    }
    sum = blockReduceSum(sum);
    float scale = (1.0f - g_pcopy[row]) / sum;
    #pragma unroll
    for (int i = 0; i < NIT4; i++) {
        int idx = i * 1024 + threadIdx.x;
        if (idx < NV4) {
            float4 v = vals[i];
            v.x *= scale; v.y *= scale; v.z *= scale; v.w *= scale;
            reinterpret_cast<float4*>(p)[idx] = v;
        }
    }
}

// ---------------- stream/event setup ----------------
struct StreamInit {
    cudaStream_t s1, s2;
    cudaEvent_t evFork, evA, evJoin, evW1, evR0, evS0;
    StreamInit() {
        cudaStreamCreateWithFlags(&s1, cudaStreamNonBlocking);
        cudaStreamCreateWithFlags(&s2, cudaStreamNonBlocking);
        cudaEventCreateWithFlags(&evFork, cudaEventDisableTiming);
        cudaEventCreateWithFlags(&evA, cudaEventDisableTiming);
        cudaEventCreateWithFlags(&evJoin, cudaEventDisableTiming);
        cudaEventCreateWithFlags(&evW1, cudaEventDisableTiming);
        cudaEventCreateWithFlags(&evR0, cudaEventDisableTiming);
        cudaEventCreateWithFlags(&evS0, cudaEventDisableTiming);
    }
};
static StreamInit g_si;

// ---------------- launch ----------------
extern "C" void kernel_launch(void* const* d_in, const int* in_sizes, int n_in,
                              void* d_out, int out_size) {
    const float* query   = (const float*)d_in[0];
    const float* membank = (const float*)d_in[1];
    const void*  mask    = d_in[2];
    const float* src_map = (const float*)d_in[3];
    const float* W_in    = (const float*)d_in[4];
    const float* W_copy  = (const float*)d_in[5];
    const float* b_copy  = (const float*)d_in[6];
    const float* W_gen   = (const float*)d_in[7];
    const float* b_gen   = (const float*)d_in[8];
    float* out = (float*)d_out;

    void *p_Ah = 0, *p_Al = 0, *p_Wgh = 0;
    void *p_Winh = 0, *p_Winl = 0, *p_Qih = 0, *p_Qil = 0, *p_Mbh = 0, *p_Mbl = 0;
    void *p_attn = 0;
    cudaGetSymbolAddress(&p_attn, g_attn);
    cudaGetSymbolAddress(&p_Ah, g_Ah);
    cudaGetSymbolAddress(&p_Al, g_Al);
    cudaGetSymbolAddress(&p_Wgh, g_Wgh);
    cudaGetSymbolAddress(&p_Winh, g_Winh);
    cudaGetSymbolAddress(&p_Winl, g_Winl);
    cudaGetSymbolAddress(&p_Qih, g_Qih);
    cudaGetSymbolAddress(&p_Qil, g_Qil);
    cudaGetSymbolAddress(&p_Mbh, g_Mbh);
    cudaGetSymbolAddress(&p_Mbl, g_Mbl);

    static bool attr_set = false;
    if (!attr_set) {
        cudaFuncSetAttribute((void*)gemm_f16x<3, 0, 2>, cudaFuncAttributeMaxDynamicSharedMemorySize, SMEM_OF(3, 2));
        cudaFuncSetAttribute((void*)gemm_f16x<3, 1, 2>, cudaFuncAttributeMaxDynamicSharedMemorySize, SMEM_OF(3, 2));
        cudaFuncSetAttribute((void*)gemm_f16x<1, 0, 3>, cudaFuncAttributeMaxDynamicSharedMemorySize, SMEM_OF(1, 3));
        attr_set = true;
    }

    cudaStream_t s0 = 0;
    cudaStream_t s1 = g_si.s1;
    cudaStream_t s2 = g_si.s2;

    // ---- fork ----
    cudaEventRecord(g_si.evFork, s0);

    // ---- stream 0: shared prerequisites ----
    aconv_kernel<<<(NROW * KK2) / 256, 256, 0, s0>>>(query, (unsigned*)p_Ah, (unsigned*)p_Al);
    pcopy_kernel<<<NROW, 256, 0, s0>>>(query, W_copy, b_copy);
    cudaEventRecord(g_si.evA, s0);

    // ---- stream 2: pack second half of W_gen ----
    cudaStreamWaitEvent(s2, g_si.evFork, 0);
    wconv_h_kernel<<<(KK2 * VH / 2) / 256, 256, 0, s2>>>(W_gen, (unsigned*)p_Wgh, V_, VH, VH);
    cudaEventRecord(g_si.evW1, s2);

    // ---- stream 1: attention branch ----
    cudaStreamWaitEvent(s1, g_si.evFork, 0);
    detect_maskmode_kernel<<<1, 512, 0, s1>>>((const unsigned int*)mask);
    srcidx_kernel<<<B_ * S_, 512, 0, s1>>>(src_map);
    wconv_kernel<<<(KK2 * 1024 / 2) / 256, 256, 0, s1>>>(W_in, (unsigned*)p_Winh, (unsigned*)p_Winl, 1024);
    packMbT_kernel<<<(B_ * KK2 * S_) / 256, 256, 0, s1>>>(membank);
    cudaStreamWaitEvent(s1, g_si.evA, 0);
    // qin = query @ W_in (fp16x3), epilogue packs hi/lo into Qih/Qil
    gemm_f16x<3, 1, 2><<<dim3(NROW / 128, 1024 / 128, 1), 256, SMEM_OF(3, 2), s1>>>(
        (const unsigned*)p_Ah, (const unsigned*)p_Al,
        (const unsigned*)p_Winh, (const unsigned*)p_Winl,
        1024, nullptr, nullptr, 0,
        (unsigned*)p_Qih, (unsigned*)p_Qil, 0, 0, 0);
    // attention logits per batch (fp16x3, z-batched)
    gemm_f16x<3, 0, 2><<<dim3(T_ / 128, S_ / 128, B_), 256, SMEM_OF(3, 2), s1>>>(
        (const unsigned*)p_Qih, (const unsigned*)p_Qil,
        (const unsigned*)p_Mbh, (const unsigned*)p_Mbl,
        S_, nullptr, (float*)p_attn, S_, nullptr, nullptr,
        (long long)T_ * KK2, (long long)KK2 * S_, (long long)T_ * S_);
    attn_softmax_scatter<<<NROW, 512, 0, s1>>>(mask, out);
    cudaEventRecord(g_si.evJoin, s1);

    // ---- stream 0: pipelined gen chain (2 row-halves x 2 col-halves), 3-stage GEMM ----
    wconv_h_kernel<<<(KK2 * VH / 2) / 256, 256, 0, s0>>>(W_gen, (unsigned*)p_Wgh, V_, 0, VH);
    // G(r0, c0)
    gemm_f16x<1, 0, 3><<<dim3(RH / 128, VH / 128, 1), 256, SMEM_OF(1, 3), s0>>>(
        (const unsigned*)p_Ah, (const unsigned*)p_Al,
        (const unsigned*)p_Wgh, (const unsigned*)p_Wgh,
        V_, b_gen, out, OUTW, nullptr, nullptr, 0, 0, 0);
    // G(r0, c1)
    cudaStreamWaitEvent(s0, g_si.evW1, 0);
    gemm_f16x<1, 0, 3><<<dim3(RH / 128, VH / 128, 1), 256, SMEM_OF(1, 3), s0>>>(
        (const unsigned*)p_Ah, (const unsigned*)p_Al,
        (const unsigned*)p_Wgh + VH, (const unsigned*)p_Wgh + VH,
        V_, b_gen + VH, out + VH, OUTW, nullptr, nullptr, 0, 0, 0);
    cudaEventRecord(g_si.evR0, s0);
    // G(r1, c0), G(r1, c1)
    gemm_f16x<1, 0, 3><<<dim3(RH / 128, VH / 128, 1), 256, SMEM_OF(1, 3), s0>>>(
        (const unsigned*)p_Ah + (size_t)RH * KK2, (const unsigned*)p_Al,
        (const unsigned*)p_Wgh, (const unsigned*)p_Wgh,
        V_, b_gen, out + (size_t)RH * OUTW, OUTW, nullptr, nullptr, 0, 0, 0);
    gemm_f16x<1, 0, 3><<<dim3(RH / 128, VH / 128, 1), 256, SMEM_OF(1, 3), s0>>>(
        (const unsigned*)p_Ah + (size_t)RH * KK2, (const unsigned*)p_Al,
        (const unsigned*)p_Wgh + VH, (const unsigned*)p_Wgh + VH,
        V_, b_gen + VH, out + (size_t)RH * OUTW + VH, OUTW, nullptr, nullptr, 0, 0, 0);
    // softmax(r0) on s2, overlapping r1 GEMMs
    cudaStreamWaitEvent(s2, g_si.evR0, 0);
    gen_softmax<<<RH, 1024, 0, s2>>>(out, 0);
    cudaEventRecord(g_si.evS0, s2);
    // softmax(r1) on s0
    gen_softmax<<<RH, 1024, 0, s0>>>(out, RH);

    // ---- join ----
    cudaStreamWaitEvent(s0, g_si.evS0, 0);
    cudaStreamWaitEvent(s0, g_si.evJoin, 0);
}